// round 3
// baseline (speedup 1.0000x reference)
#include <cuda_runtime.h>
#include <cstdint>

// Problem constants
#define B_  128
#define V_  2048
#define S_  1024
#define E_  64

// Tiling
#define KT   32            // K (vocab) chunk per stage
#define LDA  136           // smem row stride for A in floats (136 mod 32 == 8 -> conflict-free frag LDS)
#define LDB  72            // smem row stride for B in floats (72  mod 32 == 8)
#define SMEM_A_FLOATS (KT * LDA)   // 4352 per buffer
#define SMEM_B_FLOATS (KT * LDB)   // 2304 per buffer
#define SMEM_BYTES ((2 * SMEM_A_FLOATS + 2 * SMEM_B_FLOATS) * 4)   // 53248 B

__device__ __forceinline__ float tf32_rn(float x) {
    uint32_t u;
    asm("cvt.rna.tf32.f32 %0, %1;" : "=r"(u) : "f"(x));
    return __uint_as_float(u);
}

#define MMA_TF32(d, a, b)                                                     \
    asm volatile(                                                             \
        "mma.sync.aligned.m16n8k8.row.col.f32.tf32.tf32.f32 "                 \
        "{%0,%1,%2,%3},{%4,%5,%6,%7},{%8,%9},{%0,%1,%2,%3};"                  \
        : "+f"((d)[0]), "+f"((d)[1]), "+f"((d)[2]), "+f"((d)[3])              \
        : "r"((a)[0]), "r"((a)[1]), "r"((a)[2]), "r"((a)[3]),                 \
          "r"((b)[0]), "r"((b)[1]))

// CTA tile: M=128 (seq), N=64 (embed), K loop over V=2048.
// 8 warps in a 4(m) x 2(n) grid; each warp computes 32x32 via 2x4 m16n8k8 tf32 MMAs per k8.
__global__ __launch_bounds__(256, 2)
void Embedding_59476707115122_kernel(const float* __restrict__ in,
                                     const float* __restrict__ emb,
                                     float* __restrict__ out) {
    extern __shared__ float smem[];
    float* sA = smem;                         // [2][KT][LDA]
    float* sB = smem + 2 * SMEM_A_FLOATS;     // [2][KT][LDB]

    const int tid  = threadIdx.x;
    const int lane = tid & 31;
    const int wid  = tid >> 5;
    const int warp_m = wid & 3;       // 0..3 -> m offset 32*warp_m
    const int warp_n = wid >> 2;      // 0..1 -> n offset 32*warp_n
    const int g  = lane >> 2;         // group id (0..7)
    const int tg = lane & 3;          // thread-in-group (0..3)

    const int sBase = blockIdx.x * 128;
    const int b     = blockIdx.y;

    const float* inB  = in  + (size_t)b * ((size_t)V_ * S_) + sBase;  // + v*S_ + m
    float*       outB = out + (size_t)b * ((size_t)S_ * E_) + (size_t)sBase * E_;

    float acc[2][4][4];
    #pragma unroll
    for (int mt = 0; mt < 2; mt++)
        #pragma unroll
        for (int nt = 0; nt < 4; nt++)
            #pragma unroll
            for (int r = 0; r < 4; r++) acc[mt][nt][r] = 0.0f;

    float4 ra[4];   // A staging: 1024 float4 per stage, 4 per thread
    float4 rb[2];   // B staging: 512 float4 per stage, 2 per thread

    // ---- prologue: load stage 0 ----
    {
        const int vBase = 0;
        #pragma unroll
        for (int j = 0; j < 4; j++) {
            int p = tid + 256 * j;
            int k = p >> 5;
            int m4 = (p & 31) << 2;
            ra[j] = *reinterpret_cast<const float4*>(inB + (size_t)(vBase + k) * S_ + m4);
        }
        #pragma unroll
        for (int j = 0; j < 2; j++) {
            int p = tid + 256 * j;
            int k = p >> 4;
            int n4 = (p & 15) << 2;
            rb[j] = *reinterpret_cast<const float4*>(emb + (vBase + k) * E_ + n4);
        }
    }

    const int nIter = V_ / KT;   // 64
    for (int it = 0; it < nIter; it++) {
        __syncthreads();   // prior compute on this buffer done

        // ---- STS staged regs -> smem buffer (it&1), converting to tf32 (RN) ----
        {
            float* A = sA + (it & 1) * SMEM_A_FLOATS;
            float* Bm = sB + (it & 1) * SMEM_B_FLOATS;
            #pragma unroll
            for (int j = 0; j < 4; j++) {
                int p = tid + 256 * j;
                int k = p >> 5;
                int m4 = (p & 31) << 2;
                float4 v = ra[j];
                v.x = tf32_rn(v.x); v.y = tf32_rn(v.y);
                v.z = tf32_rn(v.z); v.w = tf32_rn(v.w);
                *reinterpret_cast<float4*>(A + k * LDA + m4) = v;
            }
            #pragma unroll
            for (int j = 0; j < 2; j++) {
                int p = tid + 256 * j;
                int k = p >> 4;
                int n4 = (p & 15) << 2;
                float4 v = rb[j];
                v.x = tf32_rn(v.x); v.y = tf32_rn(v.y);
                v.z = tf32_rn(v.z); v.w = tf32_rn(v.w);
                *reinterpret_cast<float4*>(Bm + k * LDB + n4) = v;
            }
        }
        __syncthreads();

        // ---- prefetch next stage from GMEM ----
        if (it + 1 < nIter) {
            const int vBase = (it + 1) * KT;
            #pragma unroll
            for (int j = 0; j < 4; j++) {
                int p = tid + 256 * j;
                int k = p >> 5;
                int m4 = (p & 31) << 2;
                ra[j] = *reinterpret_cast<const float4*>(inB + (size_t)(vBase + k) * S_ + m4);
            }
            #pragma unroll
            for (int j = 0; j < 2; j++) {
                int p = tid + 256 * j;
                int k = p >> 4;
                int n4 = (p & 15) << 2;
                rb[j] = *reinterpret_cast<const float4*>(emb + (vBase + k) * E_ + n4);
            }
        }

        // ---- compute this stage from smem ----
        {
            const float* A = sA + (it & 1) * SMEM_A_FLOATS;
            const float* Bm = sB + (it & 1) * SMEM_B_FLOATS;
            const int mBase0 = warp_m * 32;
            const int nBase0 = warp_n * 32;

            #pragma unroll
            for (int kk = 0; kk < KT; kk += 8) {
                uint32_t afrag[2][4];
                #pragma unroll
                for (int mt = 0; mt < 2; mt++) {
                    int m = mBase0 + mt * 16 + g;
                    afrag[mt][0] = __float_as_uint(A[(kk + tg) * LDA + m]);
                    afrag[mt][1] = __float_as_uint(A[(kk + tg) * LDA + m + 8]);
                    afrag[mt][2] = __float_as_uint(A[(kk + tg + 4) * LDA + m]);
                    afrag[mt][3] = __float_as_uint(A[(kk + tg + 4) * LDA + m + 8]);
                }
                uint32_t bfrag[4][2];
                #pragma unroll
                for (int nt = 0; nt < 4; nt++) {
                    int n = nBase0 + nt * 8 + g;
                    bfrag[nt][0] = __float_as_uint(Bm[(kk + tg) * LDB + n]);
                    bfrag[nt][1] = __float_as_uint(Bm[(kk + tg + 4) * LDB + n]);
                }
                #pragma unroll
                for (int mt = 0; mt < 2; mt++)
                    #pragma unroll
                    for (int nt = 0; nt < 4; nt++)
                        MMA_TF32(acc[mt][nt], afrag[mt], bfrag[nt]);
            }
        }
    }

    // ---- epilogue: write C fragments (c0,c1 / c2,c3 are adjacent columns -> float2) ----
    #pragma unroll
    for (int mt = 0; mt < 2; mt++) {
        #pragma unroll
        for (int nt = 0; nt < 4; nt++) {
            int m0 = warp_m * 32 + mt * 16 + g;
            int n0 = warp_n * 32 + nt * 8 + tg * 2;
            float2 v01 = make_float2(acc[mt][nt][0], acc[mt][nt][1]);
            float2 v23 = make_float2(acc[mt][nt][2], acc[mt][nt][3]);
            *reinterpret_cast<float2*>(outB + (size_t)m0 * E_ + n0)       = v01;
            *reinterpret_cast<float2*>(outB + (size_t)(m0 + 8) * E_ + n0) = v23;
        }
    }
}

extern "C" void kernel_launch(void* const* d_in, const int* in_sizes, int n_in,
                              void* d_out, int out_size) {
    const float* in  = (const float*)d_in[0];   // [B, V, S] f32
    const float* emb = (const float*)d_in[1];   // [V, E]    f32
    float* out = (float*)d_out;                 // [B, S, E] f32

    static bool attr_set = false;
    if (!attr_set) {
        cudaFuncSetAttribute(Embedding_59476707115122_kernel,
                             cudaFuncAttributeMaxDynamicSharedMemorySize, SMEM_BYTES);
        attr_set = true;
    }

    dim3 grid(S_ / 128, B_);   // 8 x 128 = 1024 CTAs
    Embedding_59476707115122_kernel<<<grid, 256, SMEM_BYTES>>>(in, emb, out);
}

// round 7
// speedup vs baseline: 1.2612x; 1.2612x over previous
#include <cuda_runtime.h>
#include <cstdint>

// Problem: out[b,s,e] = sum_v in[b,v,s] * emb[v,e];  B=128, V=2048, S=1024, E=64
#define B_  128
#define V_  2048
#define S_  1024
#define E_  64

#define S_TILE   256                 // M per CTA (seq)
#define KT       32                  // vocab per stage
#define NIT      (V_ / KT)           // 64 stages
#define NK8      (V_ / 8)            // 256 k8 steps total

#define LDA2         264             // smem row stride (floats); 264%32==8 -> conflict-free LDS
#define STAGE_FLOATS (KT * LDA2)     // 8448
#define NSTAGE       3
#define SMEM_BYTES   (NSTAGE * STAGE_FLOATS * 4)   // 101376

__device__ __forceinline__ float tf32_rn(float x) {
    uint32_t u;
    asm("cvt.rna.tf32.f32 %0, %1;" : "=r"(u) : "f"(x));
    return __uint_as_float(u);
}
__device__ __forceinline__ uint32_t smem_u32(const void* p) {
    uint32_t a;
    asm("{ .reg .u64 t; cvta.to.shared.u64 t, %1; cvt.u32.u64 %0, t; }" : "=r"(a) : "l"(p));
    return a;
}

#define CP_ASYNC16(dst, src) \
    asm volatile("cp.async.cg.shared.global [%0], [%1], 16;" :: "r"(dst), "l"(src))
#define CP_COMMIT()  asm volatile("cp.async.commit_group;" ::: "memory")
#define CP_WAIT1()   asm volatile("cp.async.wait_group 1;" ::: "memory")
#define CP_WAIT0()   asm volatile("cp.async.wait_group 0;" ::: "memory")

#define MMA_TF32(d, a, b)                                                     \
    asm volatile(                                                             \
        "mma.sync.aligned.m16n8k8.row.col.f32.tf32.tf32.f32 "                 \
        "{%0,%1,%2,%3},{%4,%5,%6,%7},{%8,%9},{%0,%1,%2,%3};"                  \
        : "+f"((d)[0]), "+f"((d)[1]), "+f"((d)[2]), "+f"((d)[3])              \
        : "r"((a)[0]), "r"((a)[1]), "r"((a)[2]), "r"((a)[3]),                 \
          "r"((b)[0]), "r"((b)[1]))

// ---- Precomputed B operand: emb in fragment order, tf32-RN converted ----
// g_P[(k8*8 + nt)*32 + lane] = { tf32(emb[k8*8+tg][nt*8+g]), tf32(emb[k8*8+tg+4][nt*8+g]) }
// with tg = lane&3, g = lane>>2.  Size: 256*8*32 float2 = 512 KB.
__device__ float2 g_P[NK8 * 8 * 32];

__global__ void embP_prep_kernel(const float* __restrict__ emb) {
    int t = blockIdx.x * 256 + threadIdx.x;   // 0 .. 65535
    int lane = t & 31;
    int nt   = (t >> 5) & 7;
    int k8   = t >> 8;
    int tg = lane & 3, g = lane >> 2;
    int n = nt * 8 + g;
    float2 v;
    v.x = tf32_rn(emb[(k8 * 8 + tg    ) * E_ + n]);
    v.y = tf32_rn(emb[(k8 * 8 + tg + 4) * E_ + n]);
    g_P[t] = v;
}

// ---- Main kernel ----
// CTA: 128 threads (4 warps). Tile M=256(s) x N=64(e). Warp tile 64x64 (4mt x 8nt).
// A (input) staged via cp.async into smem [k][m]; B fragments via LDG.64 from g_P.
__global__ __launch_bounds__(128, 2)
void Embedding_59476707115122_kernel(const float* __restrict__ in,
                                     float* __restrict__ out) {
    extern __shared__ float smem[];
    const uint32_t sb = smem_u32(smem);

    const int tid  = threadIdx.x;
    const int lane = tid & 31;
    const int wid  = tid >> 5;          // warp m-slice: m in [wid*64, wid*64+64)
    const int g  = lane >> 2;
    const int tg = lane & 3;

    const int sBase = blockIdx.x * S_TILE;
    const int b     = blockIdx.y;
    const float* inB  = in  + (size_t)b * ((size_t)V_ * S_) + sBase;
    float*       outB = out + (size_t)b * ((size_t)S_ * E_) + (size_t)sBase * E_;

    float acc[4][8][4];
    #pragma unroll
    for (int mt = 0; mt < 4; mt++)
        #pragma unroll
        for (int nt = 0; nt < 8; nt++)
            #pragma unroll
            for (int r = 0; r < 4; r++) acc[mt][nt][r] = 0.0f;

    // ---- prologue: issue stages 0 and 1 ----
    #pragma unroll
    for (int st = 0; st < 2; st++) {
        const int kB = st * KT;
        #pragma unroll
        for (int j = 0; j < 16; j++) {
            int t = tid + 128 * j;
            int k = t >> 6, m4 = (t & 63) << 2;
            uint32_t dst = sb + (uint32_t)((st * STAGE_FLOATS + k * LDA2 + m4) * 4);
            CP_ASYNC16(dst, inB + (size_t)(kB + k) * S_ + m4);
        }
        CP_COMMIT();
    }

    // B fragment double buffer; preload k8g = 0
    uint32_t bfr[2][8][2];
    {
        const float2* P = g_P + lane;
        #pragma unroll
        for (int nt = 0; nt < 8; nt++) {
            float2 v = P[nt * 32];
            bfr[0][nt][0] = __float_as_uint(v.x);
            bfr[0][nt][1] = __float_as_uint(v.y);
        }
    }

    for (int it = 0; it < NIT; it++) {
        // At it==NIT-1 only the current stage is pending, so wait_group 1 would
        // NOT wait for it -> must drain fully on the last iteration.
        if (it == NIT - 1) { CP_WAIT0(); } else { CP_WAIT1(); }
        __syncthreads();

        // issue stage it+2 into ring slot (it+2)%3
        if (it + 2 < NIT) {
            const int st = (it + 2) % NSTAGE;
            const int kB = (it + 2) * KT;
            #pragma unroll
            for (int j = 0; j < 16; j++) {
                int t = tid + 128 * j;
                int k = t >> 6, m4 = (t & 63) << 2;
                uint32_t dst = sb + (uint32_t)((st * STAGE_FLOATS + k * LDA2 + m4) * 4);
                CP_ASYNC16(dst, inB + (size_t)(kB + k) * S_ + m4);
            }
            CP_COMMIT();
        }

        // compute stage it
        const float* A = smem + (it % NSTAGE) * STAGE_FLOATS;
        #pragma unroll
        for (int k8 = 0; k8 < 4; k8++) {
            const int cur = k8 & 1;           // 4 k8 per stage (even) -> parity = k8&1
            const int nxt = cur ^ 1;
            const int k8g = it * 4 + k8;

            // prefetch B for k8g+1 (clamped at the last step)
            {
                const int k8n = (k8g + 1 < NK8) ? (k8g + 1) : k8g;
                const float2* P = g_P + (size_t)k8n * 256 + lane;
                #pragma unroll
                for (int nt = 0; nt < 8; nt++) {
                    float2 v = P[nt * 32];
                    bfr[nxt][nt][0] = __float_as_uint(v.x);
                    bfr[nxt][nt][1] = __float_as_uint(v.y);
                }
            }

            // A fragments for this k8 (raw f32; HW truncates to tf32 — error zero-mean)
            const int kk = k8 * 8;
            uint32_t afr[4][4];
            #pragma unroll
            for (int mt = 0; mt < 4; mt++) {
                const int m = wid * 64 + mt * 16 + g;
                afr[mt][0] = __float_as_uint(A[(kk + tg    ) * LDA2 + m    ]);
                afr[mt][1] = __float_as_uint(A[(kk + tg    ) * LDA2 + m + 8]);
                afr[mt][2] = __float_as_uint(A[(kk + tg + 4) * LDA2 + m    ]);
                afr[mt][3] = __float_as_uint(A[(kk + tg + 4) * LDA2 + m + 8]);
            }

            #pragma unroll
            for (int mt = 0; mt < 4; mt++)
                #pragma unroll
                for (int nt = 0; nt < 8; nt++)
                    MMA_TF32(acc[mt][nt], afr[mt], bfr[cur][nt]);
        }
    }

    // ---- epilogue ----
    #pragma unroll
    for (int mt = 0; mt < 4; mt++) {
        #pragma unroll
        for (int nt = 0; nt < 8; nt++) {
            const int m0 = wid * 64 + mt * 16 + g;
            const int n0 = nt * 8 + tg * 2;
            float2 v01 = make_float2(acc[mt][nt][0], acc[mt][nt][1]);
            float2 v23 = make_float2(acc[mt][nt][2], acc[mt][nt][3]);
            *reinterpret_cast<float2*>(outB + (size_t)m0 * E_ + n0)       = v01;
            *reinterpret_cast<float2*>(outB + (size_t)(m0 + 8) * E_ + n0) = v23;
        }
    }
}

extern "C" void kernel_launch(void* const* d_in, const int* in_sizes, int n_in,
                              void* d_out, int out_size) {
    const float* in  = (const float*)d_in[0];   // [B, V, S] f32
    const float* emb = (const float*)d_in[1];   // [V, E]    f32
    float* out = (float*)d_out;                 // [B, S, E] f32

    static bool attr_set = false;
    if (!attr_set) {
        cudaFuncSetAttribute(Embedding_59476707115122_kernel,
                             cudaFuncAttributeMaxDynamicSharedMemorySize, SMEM_BYTES);
        attr_set = true;
    }

    embP_prep_kernel<<<256, 256>>>(emb);

    dim3 grid(S_ / S_TILE, B_);   // 4 x 128 = 512 CTAs
    Embedding_59476707115122_kernel<<<grid, 128, SMEM_BYTES>>>(in, out);
}